// round 1
// baseline (speedup 1.0000x reference)
#include <cuda_runtime.h>
#include <cuda_bf16.h>
#include <math.h>

// Problem constants (fixed by setup_inputs)
#define BATCH 4
#define SEQ   2048
#define DMODEL 1024
#define NHEAD 16
#define HDIM  64
#define MTOT  (BATCH * SEQ)          // 8192

// -------- scratch (device globals; no allocation allowed) --------
__device__ float g_q[BATCH * NHEAD * SEQ * HDIM];   // [B,H,S,Dh]
__device__ float g_k[BATCH * NHEAD * SEQ * HDIM];
__device__ float g_v[BATCH * NHEAD * SEQ * HDIM];
__device__ float g_ctx[BATCH * SEQ * DMODEL];       // [B,S,D]

// ============================================================
// Tiled SGEMM: C[M=8192, N=1024] = A @ W + bias
// BM=BN=64, BK=16, 16x16 threads, 4x4 per thread.
// HEADS=true scatters output to [B,H,S,Dh] layout.
// ============================================================
template <bool HEADS>
__global__ __launch_bounds__(256)
void gemm_bias_kernel(const float* __restrict__ A,
                      const float* __restrict__ W,
                      const float* __restrict__ bias,
                      float* __restrict__ C)
{
    __shared__ float As[16][68];   // [k][m] transposed
    __shared__ float Ws[16][68];   // [k][n]

    const int tx = threadIdx.x;    // 0..15  (N direction)
    const int ty = threadIdx.y;    // 0..15  (M direction)
    const int t  = ty * 16 + tx;   // 0..255
    const int bx = blockIdx.x;     // N tile (0..15)
    const int by = blockIdx.y;     // M tile (0..127)

    // A-load mapping: row = t>>2 (0..63), c4 = t&3 (4 float4 along K)
    const int a_row = t >> 2;
    const int a_c4  = t & 3;
    // W-load mapping: r = t>>4 (0..15), c4 = t&15
    const int w_r  = t >> 4;
    const int w_c4 = t & 15;

    float acc[4][4];
#pragma unroll
    for (int i = 0; i < 4; i++)
#pragma unroll
        for (int j = 0; j < 4; j++) acc[i][j] = 0.0f;

    const int m_base = by * 64;
    const int n_base = bx * 64;

    for (int k0 = 0; k0 < DMODEL; k0 += 16) {
        // load A tile (64 x 16), store transposed
        float4 av = *reinterpret_cast<const float4*>(
            &A[(m_base + a_row) * DMODEL + k0 + a_c4 * 4]);
        As[a_c4 * 4 + 0][a_row] = av.x;
        As[a_c4 * 4 + 1][a_row] = av.y;
        As[a_c4 * 4 + 2][a_row] = av.z;
        As[a_c4 * 4 + 3][a_row] = av.w;
        // load W tile (16 x 64)
        float4 wv = *reinterpret_cast<const float4*>(
            &W[(k0 + w_r) * DMODEL + n_base + w_c4 * 4]);
        *reinterpret_cast<float4*>(&Ws[w_r][w_c4 * 4]) = wv;

        __syncthreads();

#pragma unroll
        for (int kk = 0; kk < 16; kk++) {
            float4 a = *reinterpret_cast<const float4*>(&As[kk][ty * 4]);
            float4 b = *reinterpret_cast<const float4*>(&Ws[kk][tx * 4]);
            acc[0][0] += a.x * b.x; acc[0][1] += a.x * b.y; acc[0][2] += a.x * b.z; acc[0][3] += a.x * b.w;
            acc[1][0] += a.y * b.x; acc[1][1] += a.y * b.y; acc[1][2] += a.y * b.z; acc[1][3] += a.y * b.w;
            acc[2][0] += a.z * b.x; acc[2][1] += a.z * b.y; acc[2][2] += a.z * b.z; acc[2][3] += a.z * b.w;
            acc[3][0] += a.w * b.x; acc[3][1] += a.w * b.y; acc[3][2] += a.w * b.z; acc[3][3] += a.w * b.w;
        }
        __syncthreads();
    }

    const int n0 = n_base + tx * 4;
    const float b0 = bias[n0 + 0];
    const float b1 = bias[n0 + 1];
    const float b2 = bias[n0 + 2];
    const float b3 = bias[n0 + 3];

#pragma unroll
    for (int i = 0; i < 4; i++) {
        const int m = m_base + ty * 4 + i;
        float4 r;
        r.x = acc[i][0] + b0;
        r.y = acc[i][1] + b1;
        r.z = acc[i][2] + b2;
        r.w = acc[i][3] + b3;
        if (HEADS) {
            const int bb = m >> 11;        // m / SEQ
            const int s  = m & (SEQ - 1);
            const int h  = n0 >> 6;        // n / HDIM
            const int d  = n0 & (HDIM - 1);
            *reinterpret_cast<float4*>(
                &C[(((bb << 4) + h) * SEQ + s) * HDIM + d]) = r;
        } else {
            *reinterpret_cast<float4*>(&C[m * DMODEL + n0]) = r;
        }
    }
}

// ============================================================
// RoPE (interleaved pairs), applied in-place on [B,H,S,Dh].
// pair p: (x0,x1)@(2p,2p+1) -> (x0*c - x1*s, x1*c + x0*s),
// angle = (s - start) * base^(-2p/Dh), only for s >= start.
// ============================================================
__global__ void rope_kernel(float* __restrict__ t, const int* __restrict__ start_p)
{
    const int idx = blockIdx.x * blockDim.x + threadIdx.x;
    const int total = BATCH * NHEAD * SEQ * (HDIM / 2);
    if (idx >= total) return;

    const int p  = idx & 31;                 // pair index 0..31
    const int s  = (idx >> 5) & (SEQ - 1);
    const int bh = idx >> 16;                // /(SEQ*32)

    const int start = *start_p;
    if (s < start) return;

    const float pos = (float)(s - start);
    // inv_freq = 10000^(-2p/64)
    const float inv_freq = expf(-((float)(2 * p) / 64.0f) * 9.2103403719761836f);
    const float ang = pos * inv_freq;
    float sn, cs;
    sincosf(ang, &sn, &cs);

    float2* ptr = reinterpret_cast<float2*>(
        &t[(bh * SEQ + s) * HDIM + 2 * p]);
    float2 x = *ptr;
    float2 y;
    y.x = x.x * cs - x.y * sn;
    y.y = x.y * cs + x.x * sn;
    *ptr = y;
}

// ============================================================
// Flash-style attention, fp32.
// grid: (SEQ/128, B*H), block: 128 threads, 1 thread per q row.
// K/V tiles of 64 rows in smem (broadcast reads).
// Output to ctx in [B,S,D] layout.
// ============================================================
__global__ __launch_bounds__(128, 1)
void attn_kernel(const float* __restrict__ q,
                 const float* __restrict__ k,
                 const float* __restrict__ v,
                 float* __restrict__ ctx)
{
    __shared__ float Ks[64][64];
    __shared__ float Vs[64][64];

    const int tid = threadIdx.x;
    const int bh  = blockIdx.y;
    const int row = blockIdx.x * 128 + tid;      // q row within sequence
    const long base = (long)bh * SEQ * HDIM;

    // q row into registers, pre-scaled by 1/sqrt(64)
    float qreg[HDIM];
    {
        const float4* qp = reinterpret_cast<const float4*>(&q[base + (long)row * HDIM]);
#pragma unroll
        for (int d4 = 0; d4 < 16; d4++) {
            float4 qv = qp[d4];
            qreg[d4 * 4 + 0] = qv.x * 0.125f;
            qreg[d4 * 4 + 1] = qv.y * 0.125f;
            qreg[d4 * 4 + 2] = qv.z * 0.125f;
            qreg[d4 * 4 + 3] = qv.w * 0.125f;
        }
    }

    float acc[HDIM];
#pragma unroll
    for (int d = 0; d < HDIM; d++) acc[d] = 0.0f;
    float m_i = -1e30f;
    float l_i = 0.0f;

    for (int kt = 0; kt < SEQ / 64; kt++) {
        __syncthreads();
        // cooperative load of K,V tiles: 64x64 floats each = 1024 float4 each
#pragma unroll
        for (int i = 0; i < 8; i++) {
            const int fid = tid + i * 128;       // 0..1023
            const int r  = fid >> 4;             // 0..63
            const int c4 = fid & 15;
            const long gofs = base + (long)(kt * 64 + r) * HDIM + c4 * 4;
            *reinterpret_cast<float4*>(&Ks[r][c4 * 4]) =
                *reinterpret_cast<const float4*>(&k[gofs]);
            *reinterpret_cast<float4*>(&Vs[r][c4 * 4]) =
                *reinterpret_cast<const float4*>(&v[gofs]);
        }
        __syncthreads();

        // scores for 64 keys
        float p[64];
        float tmax = -1e30f;
#pragma unroll
        for (int j = 0; j < 64; j++) {
            const float4* kr = reinterpret_cast<const float4*>(&Ks[j][0]);
            float s = 0.0f;
#pragma unroll
            for (int d4 = 0; d4 < 16; d4++) {
                float4 kv = kr[d4];
                s += qreg[d4 * 4 + 0] * kv.x;
                s += qreg[d4 * 4 + 1] * kv.y;
                s += qreg[d4 * 4 + 2] * kv.z;
                s += qreg[d4 * 4 + 3] * kv.w;
            }
            p[j] = s;
            tmax = fmaxf(tmax, s);
        }

        const float m_new = fmaxf(m_i, tmax);
        const float corr = __expf(m_i - m_new);
        l_i *= corr;
#pragma unroll
        for (int d = 0; d < HDIM; d++) acc[d] *= corr;

#pragma unroll
        for (int j = 0; j < 64; j++) {
            const float pj = __expf(p[j] - m_new);
            l_i += pj;
            const float4* vr = reinterpret_cast<const float4*>(&Vs[j][0]);
#pragma unroll
            for (int d4 = 0; d4 < 16; d4++) {
                float4 vv = vr[d4];
                acc[d4 * 4 + 0] += pj * vv.x;
                acc[d4 * 4 + 1] += pj * vv.y;
                acc[d4 * 4 + 2] += pj * vv.z;
                acc[d4 * 4 + 3] += pj * vv.w;
            }
        }
        m_i = m_new;
    }

    // write ctx[b][s][h*64+d]
    const float inv_l = 1.0f / l_i;
    const int bb = bh >> 4;
    const int h  = bh & 15;
    float4* op = reinterpret_cast<float4*>(
        &ctx[((long)bb * SEQ + row) * DMODEL + h * HDIM]);
#pragma unroll
    for (int d4 = 0; d4 < 16; d4++) {
        float4 r;
        r.x = acc[d4 * 4 + 0] * inv_l;
        r.y = acc[d4 * 4 + 1] * inv_l;
        r.z = acc[d4 * 4 + 2] * inv_l;
        r.w = acc[d4 * 4 + 3] * inv_l;
        op[d4] = r;
    }
}

// ============================================================
// Launch
// ============================================================
extern "C" void kernel_launch(void* const* d_in, const int* in_sizes, int n_in,
                              void* d_out, int out_size)
{
    const float* x  = (const float*)d_in[0];
    const float* Wq = (const float*)d_in[1];
    const float* bq = (const float*)d_in[2];
    const float* Wk = (const float*)d_in[3];
    const float* bk = (const float*)d_in[4];
    const float* Wv = (const float*)d_in[5];
    const float* bv = (const float*)d_in[6];
    const float* Wo = (const float*)d_in[7];
    const float* bo = (const float*)d_in[8];
    const int* rope_start = (const int*)d_in[9];
    float* out = (float*)d_out;

    float *qp, *kp, *vp, *cp;
    cudaGetSymbolAddress((void**)&qp, g_q);
    cudaGetSymbolAddress((void**)&kp, g_k);
    cudaGetSymbolAddress((void**)&vp, g_v);
    cudaGetSymbolAddress((void**)&cp, g_ctx);

    dim3 gblock(16, 16);
    dim3 ggrid(DMODEL / 64, MTOT / 64);   // (16, 128)

    gemm_bias_kernel<true><<<ggrid, gblock>>>(x, Wq, bq, qp);
    gemm_bias_kernel<true><<<ggrid, gblock>>>(x, Wk, bk, kp);
    gemm_bias_kernel<true><<<ggrid, gblock>>>(x, Wv, bv, vp);

    const int rope_total = BATCH * NHEAD * SEQ * (HDIM / 2);
    rope_kernel<<<(rope_total + 255) / 256, 256>>>(qp, rope_start);
    rope_kernel<<<(rope_total + 255) / 256, 256>>>(kp, rope_start);

    attn_kernel<<<dim3(SEQ / 128, BATCH * NHEAD), 128>>>(qp, kp, vp, cp);

    gemm_bias_kernel<false><<<ggrid, gblock>>>(cp, Wo, bo, out);
}

// round 2
// speedup vs baseline: 4.1631x; 4.1631x over previous
#include <cuda_runtime.h>
#include <cuda_bf16.h>
#include <math.h>
#include <stdint.h>

#define BATCH 4
#define SEQ   2048
#define DMODEL 1024
#define NHEAD 16
#define HDIM  64
#define MTOT  8192          // BATCH*SEQ
#define KSP   2048          // 2*DMODEL (hi|lo)

// ---------------- scratch (device globals) ----------------
__device__ __nv_bfloat16 g_xs[MTOT * KSP];                   // x split  [M][2048]
__device__ __nv_bfloat16 g_wtq[DMODEL * KSP];                // W^T split [N][2048]
__device__ __nv_bfloat16 g_wtk[DMODEL * KSP];
__device__ __nv_bfloat16 g_wtv[DMODEL * KSP];
__device__ __nv_bfloat16 g_wto[DMODEL * KSP];
__device__ __nv_bfloat16 g_qsp[BATCH * NHEAD * SEQ * 2 * HDIM]; // [B,H,S,128] hi|lo
__device__ __nv_bfloat16 g_ksp[BATCH * NHEAD * SEQ * 2 * HDIM];
__device__ __nv_bfloat16 g_vsp[BATCH * NHEAD * SEQ * 2 * HDIM];
__device__ float         g_ctx[MTOT * DMODEL];
__device__ __nv_bfloat16 g_cs[MTOT * KSP];

// ---------------- helpers ----------------
__device__ __forceinline__ uint32_t smem_u32(const void* p) {
    return (uint32_t)__cvta_generic_to_shared(p);
}
__device__ __forceinline__ void ldsm_x4(uint32_t& r0, uint32_t& r1, uint32_t& r2, uint32_t& r3, uint32_t a) {
    asm volatile("ldmatrix.sync.aligned.m8n8.x4.shared.b16 {%0,%1,%2,%3},[%4];"
                 : "=r"(r0), "=r"(r1), "=r"(r2), "=r"(r3) : "r"(a));
}
__device__ __forceinline__ void ldsm_x4t(uint32_t& r0, uint32_t& r1, uint32_t& r2, uint32_t& r3, uint32_t a) {
    asm volatile("ldmatrix.sync.aligned.m8n8.x4.trans.shared.b16 {%0,%1,%2,%3},[%4];"
                 : "=r"(r0), "=r"(r1), "=r"(r2), "=r"(r3) : "r"(a));
}
__device__ __forceinline__ void mma16816(float* c, const uint32_t* a, const uint32_t* b) {
    asm volatile(
        "mma.sync.aligned.m16n8k16.row.col.f32.bf16.bf16.f32 "
        "{%0,%1,%2,%3},{%4,%5,%6,%7},{%8,%9},{%0,%1,%2,%3};"
        : "+f"(c[0]), "+f"(c[1]), "+f"(c[2]), "+f"(c[3])
        : "r"(a[0]), "r"(a[1]), "r"(a[2]), "r"(a[3]), "r"(b[0]), "r"(b[1]));
}
// pack two fp32 into bf16x2 (hi) + residual bf16x2 (lo). x0 -> low half.
__device__ __forceinline__ void pack_pair(float x0, float x1, uint32_t& hi, uint32_t& lo) {
    uint32_t h;
    asm("cvt.rn.bf16x2.f32 %0, %1, %2;" : "=r"(h) : "f"(x1), "f"(x0));
    __nv_bfloat162 h2 = *reinterpret_cast<__nv_bfloat162*>(&h);
    float r0 = x0 - __bfloat162float(h2.x);
    float r1 = x1 - __bfloat162float(h2.y);
    uint32_t l;
    asm("cvt.rn.bf16x2.f32 %0, %1, %2;" : "=r"(l) : "f"(r1), "f"(r0));
    hi = h; lo = l;
}

// ---------------- split: fp32 [M][1024] -> bf16 [M][2048] hi|lo ----------------
__global__ __launch_bounds__(256)
void split_kernel(const float* __restrict__ in, __nv_bfloat16* __restrict__ out)
{
    int i = blockIdx.x * 256 + threadIdx.x;        // over MTOT*256 float4s
    float4 x = reinterpret_cast<const float4*>(in)[i];
    int r = i >> 8;            // 256 float4 per row
    int c = (i & 255) * 4;
    __nv_bfloat162 h0 = __floats2bfloat162_rn(x.x, x.y);
    __nv_bfloat162 h1 = __floats2bfloat162_rn(x.z, x.w);
    __nv_bfloat162 l0 = __floats2bfloat162_rn(x.x - __bfloat162float(h0.x), x.y - __bfloat162float(h0.y));
    __nv_bfloat162 l1 = __floats2bfloat162_rn(x.z - __bfloat162float(h1.x), x.w - __bfloat162float(h1.y));
    __nv_bfloat162* oh = reinterpret_cast<__nv_bfloat162*>(&out[(long)r * KSP + c]);
    oh[0] = h0; oh[1] = h1;
    __nv_bfloat162* ol = reinterpret_cast<__nv_bfloat162*>(&out[(long)r * KSP + 1024 + c]);
    ol[0] = l0; ol[1] = l1;
}

// ---------------- weight split+transpose: W[k][n] -> Wt[n][2048] ----------------
__global__ void wsplit_kernel(const float* __restrict__ W, __nv_bfloat16* __restrict__ Wt)
{
    __shared__ float tile[32][33];
    int n0 = blockIdx.x * 32, k0 = blockIdx.y * 32;
    int tx = threadIdx.x, ty = threadIdx.y;   // 32 x 8
#pragma unroll
    for (int j = 0; j < 4; j++)
        tile[ty + 8 * j][tx] = W[(long)(k0 + ty + 8 * j) * DMODEL + n0 + tx];
    __syncthreads();
#pragma unroll
    for (int j = 0; j < 4; j++) {
        int n = n0 + ty + 8 * j;
        int k = k0 + tx;
        float v = tile[tx][ty + 8 * j];
        __nv_bfloat16 h = __float2bfloat16(v);
        Wt[(long)n * KSP + k] = h;
        Wt[(long)n * KSP + 1024 + k] = __float2bfloat16(v - __bfloat162float(h));
    }
}

// ---------------- split-bf16 tensor-core GEMM ----------------
// C[M,N] = A @ W + bias, via 3 segments: Ahi*Bhi + Alo*Bhi + Ahi*Blo
// A: [M][2048] bf16, Bt: [N][2048] bf16 (W transposed).
// OUT_MODE 0: plain fp32 [M][N]
// OUT_MODE 2: heads bf16-split [B,H,S,128]
// OUT_MODE 3: heads bf16-split + rope + scale
#define NSTEP 96
template <int OUT_MODE>
__global__ __launch_bounds__(256)
void gemm_mma(const __nv_bfloat16* __restrict__ A,
              const __nv_bfloat16* __restrict__ Bt,
              const float* __restrict__ bias,
              void* __restrict__ Cout,
              const int* __restrict__ start_p,
              float scale)
{
    __shared__ __nv_bfloat16 sA[2][128][40];
    __shared__ __nv_bfloat16 sB[2][128][40];

    const int tid = threadIdx.x;
    const int lane = tid & 31;
    const int wid = tid >> 5;
    const int warp_m = wid & 1;        // 2 warps in M
    const int warp_n = wid >> 1;       // 4 warps in N
    const int m0 = blockIdx.y * 128;
    const int n0 = blockIdx.x * 128;

    float acc[4][4][4];
#pragma unroll
    for (int i = 0; i < 4; i++)
#pragma unroll
        for (int j = 0; j < 4; j++)
#pragma unroll
            for (int q = 0; q < 4; q++) acc[i][j][q] = 0.f;

    const int ldrow = tid >> 2;       // load row helpers: idx = tid + 256*i
    const int ldq   = tid & 3;

    // preload step 0
    {
        int aoff = 0, boff = 0;
        uint4 ar0 = *(const uint4*)&A [(long)(m0 + ldrow) * KSP + aoff + ldq * 8];
        uint4 ar1 = *(const uint4*)&A [(long)(m0 + 64 + ldrow) * KSP + aoff + ldq * 8];
        uint4 br0 = *(const uint4*)&Bt[(long)(n0 + ldrow) * KSP + boff + ldq * 8];
        uint4 br1 = *(const uint4*)&Bt[(long)(n0 + 64 + ldrow) * KSP + boff + ldq * 8];
        *(uint4*)&sA[0][ldrow][ldq * 8] = ar0;
        *(uint4*)&sA[0][64 + ldrow][ldq * 8] = ar1;
        *(uint4*)&sB[0][ldrow][ldq * 8] = br0;
        *(uint4*)&sB[0][64 + ldrow][ldq * 8] = br1;
    }

    int st = 0;
    for (int step = 0; step < NSTEP; step++) {
        __syncthreads();
        uint4 ar0, ar1, br0, br1;
        if (step + 1 < NSTEP) {
            int s1 = step + 1;
            int seg = s1 >> 5;
            int k0 = (s1 & 31) << 5;
            int aoff = (seg == 1 ? 1024 : 0) + k0;
            int boff = (seg == 2 ? 1024 : 0) + k0;
            ar0 = *(const uint4*)&A [(long)(m0 + ldrow) * KSP + aoff + ldq * 8];
            ar1 = *(const uint4*)&A [(long)(m0 + 64 + ldrow) * KSP + aoff + ldq * 8];
            br0 = *(const uint4*)&Bt[(long)(n0 + ldrow) * KSP + boff + ldq * 8];
            br1 = *(const uint4*)&Bt[(long)(n0 + 64 + ldrow) * KSP + boff + ldq * 8];
        }

#pragma unroll
        for (int kk = 0; kk < 32; kk += 16) {
            uint32_t af[4][4];
            const int mrow = warp_m * 64 + (lane & 15);
            const int kcol = kk + ((lane >> 4) << 3);
#pragma unroll
            for (int mt = 0; mt < 4; mt++)
                ldsm_x4(af[mt][0], af[mt][1], af[mt][2], af[mt][3],
                        smem_u32(&sA[st][mrow + mt * 16][kcol]));
            uint32_t bfr[4][2];
#pragma unroll
            for (int bt = 0; bt < 2; bt++) {
                int n = warp_n * 32 + bt * 16 + ((lane >> 4) << 3) + (lane & 7);
                int kc2 = kk + (((lane >> 3) & 1) << 3);
                uint32_t r0, r1, r2, r3;
                ldsm_x4(r0, r1, r2, r3, smem_u32(&sB[st][n][kc2]));
                bfr[2 * bt][0] = r0; bfr[2 * bt][1] = r1;
                bfr[2 * bt + 1][0] = r2; bfr[2 * bt + 1][1] = r3;
            }
#pragma unroll
            for (int mt = 0; mt < 4; mt++)
#pragma unroll
                for (int nt = 0; nt < 4; nt++)
                    mma16816(acc[mt][nt], af[mt], bfr[nt]);
        }

        if (step + 1 < NSTEP) {
            int ns = st ^ 1;
            *(uint4*)&sA[ns][ldrow][ldq * 8] = ar0;
            *(uint4*)&sA[ns][64 + ldrow][ldq * 8] = ar1;
            *(uint4*)&sB[ns][ldrow][ldq * 8] = br0;
            *(uint4*)&sB[ns][64 + ldrow][ldq * 8] = br1;
        }
        st ^= 1;
    }

    // ---------------- epilogue ----------------
    const int r_m = warp_m * 64 + (lane >> 2);
    const int c_n = warp_n * 32 + 2 * (lane & 3);
    int start = 0;
    if (OUT_MODE == 3) start = *start_p;

#pragma unroll
    for (int mt = 0; mt < 4; mt++) {
#pragma unroll
        for (int nt = 0; nt < 4; nt++) {
            const int mg = m0 + r_m + mt * 16;
            const int ng = n0 + c_n + nt * 8;
            const float b0v = bias[ng], b1v = bias[ng + 1];
            float x0 = acc[mt][nt][0] + b0v, x1 = acc[mt][nt][1] + b1v;   // row mg
            float y0 = acc[mt][nt][2] + b0v, y1 = acc[mt][nt][3] + b1v;   // row mg+8

            if (OUT_MODE == 0) {
                float* outp = (float*)Cout;
                *(float2*)&outp[(long)mg * DMODEL + ng] = make_float2(x0, x1);
                *(float2*)&outp[(long)(mg + 8) * DMODEL + ng] = make_float2(y0, y1);
            } else {
                const int b = mg >> 11, s = mg & (SEQ - 1);
                const int h = ng >> 6, d = ng & (HDIM - 1);
                const long rowb = ((long)(b * NHEAD + h) * SEQ + s) * 128;
                __nv_bfloat16* outp = (__nv_bfloat16*)Cout;
                // two rows: s (x) and s+8 (y)
#pragma unroll
                for (int rr = 0; rr < 2; rr++) {
                    float v0 = rr ? y0 : x0;
                    float v1 = rr ? y1 : x1;
                    int ss = s + rr * 8;
                    if (OUT_MODE == 3 && ss >= start) {
                        float pos = (float)(ss - start);
                        float invf = __expf(-(float)(d >> 1) * 0.28782313662425572f);
                        float sn, cs;
                        sincosf(pos * invf, &sn, &cs);
                        float t0 = v0 * cs - v1 * sn;
                        float t1 = v1 * cs + v0 * sn;
                        v0 = t0; v1 = t1;
                    }
                    v0 *= scale; v1 *= scale;
                    uint32_t hi, lo;
                    pack_pair(v0, v1, hi, lo);
                    long ro = rowb + (long)rr * 8 * 128;
                    *(uint32_t*)&outp[ro + d] = hi;
                    *(uint32_t*)&outp[ro + 64 + d] = lo;
                }
            }
        }
    }
}

// ---------------- flash attention (split-bf16 mma) ----------------
// grid (SEQ/64, B*H), 128 threads (4 warps, 16 q-rows each)
__global__ __launch_bounds__(128)
void attn_mma(const __nv_bfloat16* __restrict__ qs,
              const __nv_bfloat16* __restrict__ ks,
              const __nv_bfloat16* __restrict__ vs,
              float* __restrict__ ctx)
{
    __shared__ __nv_bfloat16 sK[64][136];
    __shared__ __nv_bfloat16 sV[64][136];

    const int tid = threadIdx.x;
    const int lane = tid & 31;
    const int wid = tid >> 5;
    const int qb = blockIdx.x;
    const int bh = blockIdx.y;

    // stage Q tile into sK, then load fragments to registers
    {
        const __nv_bfloat16* qg = qs + ((long)bh * SEQ + qb * 64) * 128;
#pragma unroll
        for (int i = 0; i < 8; i++) {
            int u = tid + i * 128;
            int r = u >> 4, c = (u & 15) * 8;
            *(uint4*)&sK[r][c] = *(const uint4*)&qg[(long)r * 128 + c];
        }
    }
    __syncthreads();
    uint32_t qhi[4][4], qlo[4][4];
    {
        const int mrow = wid * 16 + (lane & 15);
        const int kadd = (lane >> 4) << 3;
#pragma unroll
        for (int kc = 0; kc < 4; kc++) {
            ldsm_x4(qhi[kc][0], qhi[kc][1], qhi[kc][2], qhi[kc][3],
                    smem_u32(&sK[mrow][kc * 16 + kadd]));
            ldsm_x4(qlo[kc][0], qlo[kc][1], qlo[kc][2], qlo[kc][3],
                    smem_u32(&sK[mrow][64 + kc * 16 + kadd]));
        }
    }

    float O[8][4];
#pragma unroll
    for (int i = 0; i < 8; i++)
#pragma unroll
        for (int j = 0; j < 4; j++) O[i][j] = 0.f;
    float m0 = -1e30f, m1 = -1e30f, l0 = 0.f, l1 = 0.f;

    for (int kt = 0; kt < SEQ / 64; kt++) {
        __syncthreads();
        {
            const __nv_bfloat16* kg = ks + ((long)bh * SEQ + kt * 64) * 128;
            const __nv_bfloat16* vg = vs + ((long)bh * SEQ + kt * 64) * 128;
#pragma unroll
            for (int i = 0; i < 8; i++) {
                int u = tid + i * 128;
                int r = u >> 4, c = (u & 15) * 8;
                *(uint4*)&sK[r][c] = *(const uint4*)&kg[(long)r * 128 + c];
                *(uint4*)&sV[r][c] = *(const uint4*)&vg[(long)r * 128 + c];
            }
        }
        __syncthreads();

        float S[8][4];
#pragma unroll
        for (int i = 0; i < 8; i++)
#pragma unroll
            for (int j = 0; j < 4; j++) S[i][j] = 0.f;

        // QK: (qhi+qlo)*Khi then qhi*Klo
#pragma unroll
        for (int kc = 0; kc < 4; kc++) {
            uint32_t b4[4][4];
#pragma unroll
            for (int bt = 0; bt < 4; bt++) {
                int n = bt * 16 + ((lane >> 4) << 3) + (lane & 7);
                int kcol = kc * 16 + (((lane >> 3) & 1) << 3);
                ldsm_x4(b4[bt][0], b4[bt][1], b4[bt][2], b4[bt][3], smem_u32(&sK[n][kcol]));
            }
#pragma unroll
            for (int bt = 0; bt < 4; bt++) {
                mma16816(S[2 * bt],     qhi[kc], &b4[bt][0]);
                mma16816(S[2 * bt + 1], qhi[kc], &b4[bt][2]);
                mma16816(S[2 * bt],     qlo[kc], &b4[bt][0]);
                mma16816(S[2 * bt + 1], qlo[kc], &b4[bt][2]);
            }
        }
#pragma unroll
        for (int kc = 0; kc < 4; kc++) {
            uint32_t b4[4][4];
#pragma unroll
            for (int bt = 0; bt < 4; bt++) {
                int n = bt * 16 + ((lane >> 4) << 3) + (lane & 7);
                int kcol = 64 + kc * 16 + (((lane >> 3) & 1) << 3);
                ldsm_x4(b4[bt][0], b4[bt][1], b4[bt][2], b4[bt][3], smem_u32(&sK[n][kcol]));
            }
#pragma unroll
            for (int bt = 0; bt < 4; bt++) {
                mma16816(S[2 * bt],     qhi[kc], &b4[bt][0]);
                mma16816(S[2 * bt + 1], qhi[kc], &b4[bt][2]);
            }
        }

        // online softmax (rows lane/4 and lane/4+8)
        float tmax0 = -1e30f, tmax1 = -1e30f;
#pragma unroll
        for (int nt = 0; nt < 8; nt++) {
            tmax0 = fmaxf(tmax0, fmaxf(S[nt][0], S[nt][1]));
            tmax1 = fmaxf(tmax1, fmaxf(S[nt][2], S[nt][3]));
        }
        tmax0 = fmaxf(tmax0, __shfl_xor_sync(0xffffffffu, tmax0, 1));
        tmax0 = fmaxf(tmax0, __shfl_xor_sync(0xffffffffu, tmax0, 2));
        tmax1 = fmaxf(tmax1, __shfl_xor_sync(0xffffffffu, tmax1, 1));
        tmax1 = fmaxf(tmax1, __shfl_xor_sync(0xffffffffu, tmax1, 2));
        const float mn0 = fmaxf(m0, tmax0);
        const float mn1 = fmaxf(m1, tmax1);
        const float corr0 = __expf(m0 - mn0);
        const float corr1 = __expf(m1 - mn1);
        m0 = mn0; m1 = mn1;
#pragma unroll
        for (int nt = 0; nt < 8; nt++) {
            O[nt][0] *= corr0; O[nt][1] *= corr0;
            O[nt][2] *= corr1; O[nt][3] *= corr1;
        }

        float sum0 = 0.f, sum1 = 0.f;
        uint32_t phi[4][4], plo[4][4];
#pragma unroll
        for (int bt = 0; bt < 4; bt++) {
            float p00 = __expf(S[2 * bt][0] - mn0), p01 = __expf(S[2 * bt][1] - mn0);
            float p02 = __expf(S[2 * bt][2] - mn1), p03 = __expf(S[2 * bt][3] - mn1);
            float p10 = __expf(S[2 * bt + 1][0] - mn0), p11 = __expf(S[2 * bt + 1][1] - mn0);
            float p12 = __expf(S[2 * bt + 1][2] - mn1), p13 = __expf(S[2 * bt + 1][3] - mn1);
            sum0 += p00 + p01 + p10 + p11;
            sum1 += p02 + p03 + p12 + p13;
            pack_pair(p00, p01, phi[bt][0], plo[bt][0]);
            pack_pair(p02, p03, phi[bt][1], plo[bt][1]);
            pack_pair(p10, p11, phi[bt][2], plo[bt][2]);
            pack_pair(p12, p13, phi[bt][3], plo[bt][3]);
        }
        sum0 += __shfl_xor_sync(0xffffffffu, sum0, 1);
        sum0 += __shfl_xor_sync(0xffffffffu, sum0, 2);
        sum1 += __shfl_xor_sync(0xffffffffu, sum1, 1);
        sum1 += __shfl_xor_sync(0xffffffffu, sum1, 2);
        l0 = l0 * corr0 + sum0;
        l1 = l1 * corr1 + sum1;

        // AV: (phi+plo)*Vhi then phi*Vlo
#pragma unroll
        for (int kc = 0; kc < 4; kc++) {
            uint32_t vb[4][4];
#pragma unroll
            for (int ntp = 0; ntp < 4; ntp++) {
                int key = kc * 16 + ((lane >> 3) & 1) * 8 + (lane & 7);
                int col = ntp * 16 + ((lane >> 4) << 3);
                ldsm_x4t(vb[ntp][0], vb[ntp][1], vb[ntp][2], vb[ntp][3], smem_u32(&sV[key][col]));
            }
#pragma unroll
            for (int ntp = 0; ntp < 4; ntp++) {
                mma16816(O[2 * ntp],     phi[kc], &vb[ntp][0]);
                mma16816(O[2 * ntp + 1], phi[kc], &vb[ntp][2]);
                mma16816(O[2 * ntp],     plo[kc], &vb[ntp][0]);
                mma16816(O[2 * ntp + 1], plo[kc], &vb[ntp][2]);
            }
        }
#pragma unroll
        for (int kc = 0; kc < 4; kc++) {
            uint32_t vb[4][4];
#pragma unroll
            for (int ntp = 0; ntp < 4; ntp++) {
                int key = kc * 16 + ((lane >> 3) & 1) * 8 + (lane & 7);
                int col = 64 + ntp * 16 + ((lane >> 4) << 3);
                ldsm_x4t(vb[ntp][0], vb[ntp][1], vb[ntp][2], vb[ntp][3], smem_u32(&sV[key][col]));
            }
#pragma unroll
            for (int ntp = 0; ntp < 4; ntp++) {
                mma16816(O[2 * ntp],     phi[kc], &vb[ntp][0]);
                mma16816(O[2 * ntp + 1], phi[kc], &vb[ntp][2]);
            }
        }
    }

    // write ctx [B][S][H*64]
    const float inv0 = 1.f / l0;
    const float inv1 = 1.f / l1;
    const int b = bh >> 4, h = bh & 15;
    const int s0 = qb * 64 + wid * 16 + (lane >> 2);
    float* base0 = ctx + ((long)b * SEQ + s0) * DMODEL + h * HDIM;
    float* base1 = base0 + (long)8 * DMODEL;
#pragma unroll
    for (int nt = 0; nt < 8; nt++) {
        int c = nt * 8 + 2 * (lane & 3);
        *(float2*)&base0[c] = make_float2(O[nt][0] * inv0, O[nt][1] * inv0);
        *(float2*)&base1[c] = make_float2(O[nt][2] * inv1, O[nt][3] * inv1);
    }
}

// ---------------- launch ----------------
extern "C" void kernel_launch(void* const* d_in, const int* in_sizes, int n_in,
                              void* d_out, int out_size)
{
    const float* x  = (const float*)d_in[0];
    const float* Wq = (const float*)d_in[1];
    const float* bq = (const float*)d_in[2];
    const float* Wk = (const float*)d_in[3];
    const float* bk = (const float*)d_in[4];
    const float* Wv = (const float*)d_in[5];
    const float* bv = (const float*)d_in[6];
    const float* Wo = (const float*)d_in[7];
    const float* bo = (const float*)d_in[8];
    const int* rope_start = (const int*)d_in[9];
    float* out = (float*)d_out;

    __nv_bfloat16 *xs, *wtq, *wtk, *wtv, *wto, *qsp, *ksp, *vsp, *cs;
    float *ctx;
    cudaGetSymbolAddress((void**)&xs,  g_xs);
    cudaGetSymbolAddress((void**)&wtq, g_wtq);
    cudaGetSymbolAddress((void**)&wtk, g_wtk);
    cudaGetSymbolAddress((void**)&wtv, g_wtv);
    cudaGetSymbolAddress((void**)&wto, g_wto);
    cudaGetSymbolAddress((void**)&qsp, g_qsp);
    cudaGetSymbolAddress((void**)&ksp, g_ksp);
    cudaGetSymbolAddress((void**)&vsp, g_vsp);
    cudaGetSymbolAddress((void**)&ctx, g_ctx);
    cudaGetSymbolAddress((void**)&cs,  g_cs);

    // splits
    split_kernel<<<MTOT, 256>>>(x, xs);       // MTOT*1024/4 / 256 = MTOT blocks
    dim3 wgrid(32, 32), wblock(32, 8);
    wsplit_kernel<<<wgrid, wblock>>>(Wq, wtq);
    wsplit_kernel<<<wgrid, wblock>>>(Wk, wtk);
    wsplit_kernel<<<wgrid, wblock>>>(Wv, wtv);
    wsplit_kernel<<<wgrid, wblock>>>(Wo, wto);

    // projections (tensor core, fused rope+scale+split epilogue)
    dim3 ggrid(DMODEL / 128, MTOT / 128);     // (8, 64)
    gemm_mma<3><<<ggrid, 256>>>(xs, wtq, bq, qsp, rope_start, 0.125f);
    gemm_mma<3><<<ggrid, 256>>>(xs, wtk, bk, ksp, rope_start, 1.0f);
    gemm_mma<2><<<ggrid, 256>>>(xs, wtv, bv, vsp, rope_start, 1.0f);

    // attention
    attn_mma<<<dim3(SEQ / 64, BATCH * NHEAD), 128>>>(qsp, ksp, vsp, ctx);

    // output projection
    split_kernel<<<MTOT, 256>>>(ctx, cs);
    gemm_mma<0><<<ggrid, 256>>>(cs, wto, bo, out, rope_start, 1.0f);
}

// round 6
// speedup vs baseline: 4.7848x; 1.1493x over previous
#include <cuda_runtime.h>
#include <cuda_bf16.h>
#include <math.h>
#include <stdint.h>

#define BATCH 4
#define SEQ   2048
#define DMODEL 1024
#define NHEAD 16
#define HDIM  64
#define MTOT  8192          // BATCH*SEQ
#define KSP   2048          // 2*DMODEL (hi|lo)

// ---------------- scratch (device globals) ----------------
__device__ __nv_bfloat16 g_xs[MTOT * KSP];                   // x split  [M][2048]
__device__ __nv_bfloat16 g_wtq[DMODEL * KSP];                // W^T split [N][2048]
__device__ __nv_bfloat16 g_wtk[DMODEL * KSP];
__device__ __nv_bfloat16 g_wtv[DMODEL * KSP];
__device__ __nv_bfloat16 g_wto[DMODEL * KSP];
__device__ __nv_bfloat16 g_qsp[BATCH * NHEAD * SEQ * 2 * HDIM]; // [B,H,S,128] hi|lo
__device__ __nv_bfloat16 g_ksp[BATCH * NHEAD * SEQ * 2 * HDIM];
__device__ __nv_bfloat16 g_vsp[BATCH * NHEAD * SEQ * 2 * HDIM];
__device__ __nv_bfloat16 g_cs[MTOT * KSP];                   // ctx split [M][2048]

// ---------------- helpers ----------------
__device__ __forceinline__ uint32_t smem_u32(const void* p) {
    return (uint32_t)__cvta_generic_to_shared(p);
}
__device__ __forceinline__ void cp16(uint32_t s, const void* g) {
    asm volatile("cp.async.cg.shared.global [%0], [%1], 16;" :: "r"(s), "l"(g));
}
__device__ __forceinline__ void cp_commit() {
    asm volatile("cp.async.commit_group;" ::: "memory");
}
__device__ __forceinline__ void cp_wait1() {
    asm volatile("cp.async.wait_group 1;" ::: "memory");
}
__device__ __forceinline__ void cp_wait0() {
    asm volatile("cp.async.wait_group 0;" ::: "memory");
}
__device__ __forceinline__ void ldsm_x4(uint32_t& r0, uint32_t& r1, uint32_t& r2, uint32_t& r3, uint32_t a) {
    asm volatile("ldmatrix.sync.aligned.m8n8.x4.shared.b16 {%0,%1,%2,%3},[%4];"
                 : "=r"(r0), "=r"(r1), "=r"(r2), "=r"(r3) : "r"(a));
}
__device__ __forceinline__ void ldsm_x4t(uint32_t& r0, uint32_t& r1, uint32_t& r2, uint32_t& r3, uint32_t a) {
    asm volatile("ldmatrix.sync.aligned.m8n8.x4.trans.shared.b16 {%0,%1,%2,%3},[%4];"
                 : "=r"(r0), "=r"(r1), "=r"(r2), "=r"(r3) : "r"(a));
}
__device__ __forceinline__ void mma16816(float* c, const uint32_t* a, const uint32_t* b) {
    asm volatile(
        "mma.sync.aligned.m16n8k16.row.col.f32.bf16.bf16.f32 "
        "{%0,%1,%2,%3},{%4,%5,%6,%7},{%8,%9},{%0,%1,%2,%3};"
        : "+f"(c[0]), "+f"(c[1]), "+f"(c[2]), "+f"(c[3])
        : "r"(a[0]), "r"(a[1]), "r"(a[2]), "r"(a[3]), "r"(b[0]), "r"(b[1]));
}
__device__ __forceinline__ void pack_pair(float x0, float x1, uint32_t& hi, uint32_t& lo) {
    uint32_t h;
    asm("cvt.rn.bf16x2.f32 %0, %1, %2;" : "=r"(h) : "f"(x1), "f"(x0));
    __nv_bfloat162 h2 = *reinterpret_cast<__nv_bfloat162*>(&h);
    float r0 = x0 - __bfloat162float(h2.x);
    float r1 = x1 - __bfloat162float(h2.y);
    uint32_t l;
    asm("cvt.rn.bf16x2.f32 %0, %1, %2;" : "=r"(l) : "f"(r1), "f"(r0));
    hi = h; lo = l;
}

// ---------------- split: fp32 [M][1024] -> bf16 [M][2048] hi|lo ----------------
__global__ __launch_bounds__(256)
void split_kernel(const float* __restrict__ in, __nv_bfloat16* __restrict__ out)
{
    int i = blockIdx.x * 256 + threadIdx.x;
    float4 x = reinterpret_cast<const float4*>(in)[i];
    int r = i >> 8;
    int c = (i & 255) * 4;
    __nv_bfloat162 h0 = __floats2bfloat162_rn(x.x, x.y);
    __nv_bfloat162 h1 = __floats2bfloat162_rn(x.z, x.w);
    __nv_bfloat162 l0 = __floats2bfloat162_rn(x.x - __bfloat162float(h0.x), x.y - __bfloat162float(h0.y));
    __nv_bfloat162 l1 = __floats2bfloat162_rn(x.z - __bfloat162float(h1.x), x.w - __bfloat162float(h1.y));
    __nv_bfloat162* oh = reinterpret_cast<__nv_bfloat162*>(&out[(long)r * KSP + c]);
    oh[0] = h0; oh[1] = h1;
    __nv_bfloat162* ol = reinterpret_cast<__nv_bfloat162*>(&out[(long)r * KSP + 1024 + c]);
    ol[0] = l0; ol[1] = l1;
}

// ---------------- fused weight split+transpose (4 weights, blockIdx.z) ----------------
__global__ void wsplit_kernel(const float* __restrict__ W0, const float* __restrict__ W1,
                              const float* __restrict__ W2, const float* __restrict__ W3,
                              __nv_bfloat16* __restrict__ T0, __nv_bfloat16* __restrict__ T1,
                              __nv_bfloat16* __restrict__ T2, __nv_bfloat16* __restrict__ T3)
{
    const float* W = (blockIdx.z == 0) ? W0 : (blockIdx.z == 1) ? W1 : (blockIdx.z == 2) ? W2 : W3;
    __nv_bfloat16* Wt = (blockIdx.z == 0) ? T0 : (blockIdx.z == 1) ? T1 : (blockIdx.z == 2) ? T2 : T3;

    __shared__ float tile[32][33];
    int n0 = blockIdx.x * 32, k0 = blockIdx.y * 32;
    int tx = threadIdx.x, ty = threadIdx.y;   // 32 x 8
#pragma unroll
    for (int j = 0; j < 4; j++)
        tile[ty + 8 * j][tx] = W[(long)(k0 + ty + 8 * j) * DMODEL + n0 + tx];
    __syncthreads();
#pragma unroll
    for (int j = 0; j < 4; j++) {
        int n = n0 + ty + 8 * j;
        int k = k0 + tx;
        float v = tile[tx][ty + 8 * j];
        __nv_bfloat16 h = __float2bfloat16(v);
        Wt[(long)n * KSP + k] = h;
        Wt[(long)n * KSP + 1024 + k] = __float2bfloat16(v - __bfloat162float(h));
    }
}

// ---------------- split-bf16 tensor-core GEMM (3-stage cp.async, BK=64) ----------------
// OUT_MODE 0: plain fp32 [M][N]; 2: heads bf16-split; 3: heads + rope + scale
#define NSTEP 48
#define GPAD  72
#define GEMM_SMEM (3 * 128 * GPAD * 2 * 2)

template <int OUT_MODE>
__global__ __launch_bounds__(256, 2)
void gemm_mma(const __nv_bfloat16* __restrict__ A,
              const __nv_bfloat16* __restrict__ Bt,
              const float* __restrict__ bias,
              void* __restrict__ Cout,
              const int* __restrict__ start_p,
              float scale)
{
    extern __shared__ __align__(16) char smem_raw[];
    __nv_bfloat16* sA = reinterpret_cast<__nv_bfloat16*>(smem_raw);                // [3][128][72]
    __nv_bfloat16* sB = sA + 3 * 128 * GPAD;                                       // [3][128][72]

    const int tid = threadIdx.x;
    const int lane = tid & 31;
    const int wid = tid >> 5;
    const int warp_m = wid & 1;
    const int warp_n = wid >> 1;
    const int m0 = blockIdx.y * 128;
    const int n0 = blockIdx.x * 128;

    float acc[4][4][4];
#pragma unroll
    for (int i = 0; i < 4; i++)
#pragma unroll
        for (int j = 0; j < 4; j++)
#pragma unroll
            for (int q = 0; q < 4; q++) acc[i][j][q] = 0.f;

    const int ldrow = tid >> 3;   // 0..31
    const int ldc8  = tid & 7;    // chunk col (64 cols per stage)

    auto issue = [&](int st, int step) {
        const int seg = step >> 4;
        const int ks  = (step & 15) << 6;
        const int aoff = (seg == 1 ? 1024 : 0) + ks;
        const int boff = (seg == 2 ? 1024 : 0) + ks;
        __nv_bfloat16* sAs = sA + st * 128 * GPAD;
        __nv_bfloat16* sBs = sB + st * 128 * GPAD;
#pragma unroll
        for (int i = 0; i < 4; i++) {
            const int r = ldrow + 32 * i;
            cp16(smem_u32(&sAs[r * GPAD + ldc8 * 8]),
                 &A[(long)(m0 + r) * KSP + aoff + ldc8 * 8]);
            cp16(smem_u32(&sBs[r * GPAD + ldc8 * 8]),
                 &Bt[(long)(n0 + r) * KSP + boff + ldc8 * 8]);
        }
    };

    issue(0, 0); cp_commit();
    issue(1, 1); cp_commit();

    for (int step = 0; step < NSTEP; step++) {
        if (step == NSTEP - 1) cp_wait0(); else cp_wait1();
        __syncthreads();
        if (step + 2 < NSTEP) { issue((step + 2) % 3, step + 2); cp_commit(); }

        const int st = step % 3;
        const __nv_bfloat16* sAs = sA + st * 128 * GPAD;
        const __nv_bfloat16* sBs = sB + st * 128 * GPAD;

#pragma unroll
        for (int kk = 0; kk < 64; kk += 16) {
            uint32_t af[4][4];
            const int mrow = warp_m * 64 + (lane & 15);
            const int kcol = kk + ((lane >> 4) << 3);
#pragma unroll
            for (int mt = 0; mt < 4; mt++)
                ldsm_x4(af[mt][0], af[mt][1], af[mt][2], af[mt][3],
                        smem_u32(&sAs[(mrow + mt * 16) * GPAD + kcol]));
            uint32_t bfr[4][2];
#pragma unroll
            for (int bt = 0; bt < 2; bt++) {
                int n = warp_n * 32 + bt * 16 + ((lane >> 4) << 3) + (lane & 7);
                int kc2 = kk + (((lane >> 3) & 1) << 3);
                uint32_t r0, r1, r2, r3;
                ldsm_x4(r0, r1, r2, r3, smem_u32(&sBs[n * GPAD + kc2]));
                bfr[2 * bt][0] = r0; bfr[2 * bt][1] = r1;
                bfr[2 * bt + 1][0] = r2; bfr[2 * bt + 1][1] = r3;
            }
#pragma unroll
            for (int mt = 0; mt < 4; mt++)
#pragma unroll
                for (int nt = 0; nt < 4; nt++)
                    mma16816(acc[mt][nt], af[mt], bfr[nt]);
        }
    }

    // ---------------- epilogue ----------------
    const int r_m = warp_m * 64 + (lane >> 2);
    const int c_n = warp_n * 32 + 2 * (lane & 3);
    int start = 0;
    if (OUT_MODE == 3) start = *start_p;

#pragma unroll
    for (int mt = 0; mt < 4; mt++) {
#pragma unroll
        for (int nt = 0; nt < 4; nt++) {
            const int mg = m0 + r_m + mt * 16;
            const int ng = n0 + c_n + nt * 8;
            const float b0v = bias[ng], b1v = bias[ng + 1];
            float x0 = acc[mt][nt][0] + b0v, x1 = acc[mt][nt][1] + b1v;
            float y0 = acc[mt][nt][2] + b0v, y1 = acc[mt][nt][3] + b1v;

            if (OUT_MODE == 0) {
                float* outp = (float*)Cout;
                *(float2*)&outp[(long)mg * DMODEL + ng] = make_float2(x0, x1);
                *(float2*)&outp[(long)(mg + 8) * DMODEL + ng] = make_float2(y0, y1);
            } else {
                const int b = mg >> 11, s = mg & (SEQ - 1);
                const int h = ng >> 6, d = ng & (HDIM - 1);
                const long rowb = ((long)(b * NHEAD + h) * SEQ + s) * 128;
                __nv_bfloat16* outp = (__nv_bfloat16*)Cout;
#pragma unroll
                for (int rr = 0; rr < 2; rr++) {
                    float v0 = rr ? y0 : x0;
                    float v1 = rr ? y1 : x1;
                    int ss = s + rr * 8;
                    if (OUT_MODE == 3 && ss >= start) {
                        float pos = (float)(ss - start);
                        float invf = __expf(-(float)(d >> 1) * 0.28782313662425572f);
                        float sn, cs;
                        sincosf(pos * invf, &sn, &cs);
                        float t0 = v0 * cs - v1 * sn;
                        float t1 = v1 * cs + v0 * sn;
                        v0 = t0; v1 = t1;
                    }
                    v0 *= scale; v1 *= scale;
                    uint32_t hi, lo;
                    pack_pair(v0, v1, hi, lo);
                    long ro = rowb + (long)rr * 8 * 128;
                    *(uint32_t*)&outp[ro + d] = hi;
                    *(uint32_t*)&outp[ro + 64 + d] = lo;
                }
            }
        }
    }
}

// ---------------- flash attention (split-bf16 mma, cp.async 3-stage) ----------------
// grid (SEQ/128, B*H), 256 threads (8 warps, 16 q-rows each)
#define APAD 136
#define ATTN_SMEM (3 * 64 * APAD * 2 * 2)

__global__ __launch_bounds__(256, 1)
void attn_mma(const __nv_bfloat16* __restrict__ qs,
              const __nv_bfloat16* __restrict__ ks,
              const __nv_bfloat16* __restrict__ vs,
              __nv_bfloat16* __restrict__ cs)
{
    extern __shared__ __align__(16) char smem_raw[];
    __nv_bfloat16* sK = reinterpret_cast<__nv_bfloat16*>(smem_raw);   // [3][64][136]
    __nv_bfloat16* sV = sK + 3 * 64 * APAD;                           // [3][64][136]

    const int tid = threadIdx.x;
    const int lane = tid & 31;
    const int wid = tid >> 5;
    const int qb = blockIdx.x;
    const int bh = blockIdx.y;
    const long hbase = (long)bh * SEQ * 128;

    // stage Q (128x128) into sK rows 0..127 (spans stages 0-1)
    // FIXED: uint4 = 8 bf16 elements -> stride 8 elements, 8 chunks per 64-col half
    {
        const __nv_bfloat16* qg = qs + hbase + (long)qb * 128 * 128;
        const int r = tid >> 1;              // 0..127
        const int c = (tid & 1) * 64;
#pragma unroll
        for (int i = 0; i < 8; i++)
            *(uint4*)&sK[r * APAD + c + i * 8] = *(const uint4*)&qg[(long)r * 128 + c + i * 8];
    }
    __syncthreads();
    uint32_t qhi[4][4], qlo[4][4];
    {
        const int mrow = wid * 16 + (lane & 15);
        const int kadd = (lane >> 4) << 3;
#pragma unroll
        for (int kc = 0; kc < 4; kc++) {
            ldsm_x4(qhi[kc][0], qhi[kc][1], qhi[kc][2], qhi[kc][3],
                    smem_u32(&sK[mrow * APAD + kc * 16 + kadd]));
            ldsm_x4(qlo[kc][0], qlo[kc][1], qlo[kc][2], qlo[kc][3],
                    smem_u32(&sK[mrow * APAD + 64 + kc * 16 + kadd]));
        }
    }
    __syncthreads();

    // full 64 rows x 128 cols (16 chunks of 8 bf16) per stage
    const int ldrow  = tid >> 4;   // 0..15
    const int ldc16  = tid & 15;   // 0..15 -> covers 128 cols
    auto issue = [&](int st, int kt) {
        const __nv_bfloat16* kg = ks + hbase + (long)kt * 64 * 128;
        const __nv_bfloat16* vg = vs + hbase + (long)kt * 64 * 128;
        __nv_bfloat16* sKs = sK + st * 64 * APAD;
        __nv_bfloat16* sVs = sV + st * 64 * APAD;
#pragma unroll
        for (int i = 0; i < 4; i++) {
            const int r = ldrow + 16 * i;    // 0..63
            cp16(smem_u32(&sKs[r * APAD + ldc16 * 8]), &kg[(long)r * 128 + ldc16 * 8]);
            cp16(smem_u32(&sVs[r * APAD + ldc16 * 8]), &vg[(long)r * 128 + ldc16 * 8]);
        }
    };

    float O[8][4];
#pragma unroll
    for (int i = 0; i < 8; i++)
#pragma unroll
        for (int j = 0; j < 4; j++) O[i][j] = 0.f;
    float m0 = -1e30f, m1 = -1e30f, l0 = 0.f, l1 = 0.f;

    issue(0, 0); cp_commit();
    issue(1, 1); cp_commit();

    const int NT = SEQ / 64;   // 32
    for (int kt = 0; kt < NT; kt++) {
        if (kt == NT - 1) cp_wait0(); else cp_wait1();
        __syncthreads();
        if (kt + 2 < NT) { issue((kt + 2) % 3, kt + 2); cp_commit(); }

        const int st = kt % 3;
        const __nv_bfloat16* Kst = sK + st * 64 * APAD;
        const __nv_bfloat16* Vst = sV + st * 64 * APAD;

        float S[8][4];
#pragma unroll
        for (int i = 0; i < 8; i++)
#pragma unroll
            for (int j = 0; j < 4; j++) S[i][j] = 0.f;

        // QK: qhi*Khi + qlo*Khi, then qhi*Klo
#pragma unroll
        for (int kc = 0; kc < 4; kc++) {
            uint32_t b4[4][4];
#pragma unroll
            for (int bt = 0; bt < 4; bt++) {
                int n = bt * 16 + ((lane >> 4) << 3) + (lane & 7);
                int kcol = kc * 16 + (((lane >> 3) & 1) << 3);
                ldsm_x4(b4[bt][0], b4[bt][1], b4[bt][2], b4[bt][3],
                        smem_u32(&Kst[n * APAD + kcol]));
            }
#pragma unroll
            for (int bt = 0; bt < 4; bt++) {
                mma16816(S[2 * bt],     qhi[kc], &b4[bt][0]);
                mma16816(S[2 * bt + 1], qhi[kc], &b4[bt][2]);
                mma16816(S[2 * bt],     qlo[kc], &b4[bt][0]);
                mma16816(S[2 * bt + 1], qlo[kc], &b4[bt][2]);
            }
        }
#pragma unroll
        for (int kc = 0; kc < 4; kc++) {
            uint32_t b4[4][4];
#pragma unroll
            for (int bt = 0; bt < 4; bt++) {
                int n = bt * 16 + ((lane >> 4) << 3) + (lane & 7);
                int kcol = 64 + kc * 16 + (((lane >> 3) & 1) << 3);
                ldsm_x4(b4[bt][0], b4[bt][1], b4[bt][2], b4[bt][3],
                        smem_u32(&Kst[n * APAD + kcol]));
            }
#pragma unroll
            for (int bt = 0; bt < 4; bt++) {
                mma16816(S[2 * bt],     qhi[kc], &b4[bt][0]);
                mma16816(S[2 * bt + 1], qhi[kc], &b4[bt][2]);
            }
        }

        // online softmax
        float tmax0 = -1e30f, tmax1 = -1e30f;
#pragma unroll
        for (int nt = 0; nt < 8; nt++) {
            tmax0 = fmaxf(tmax0, fmaxf(S[nt][0], S[nt][1]));
            tmax1 = fmaxf(tmax1, fmaxf(S[nt][2], S[nt][3]));
        }
        tmax0 = fmaxf(tmax0, __shfl_xor_sync(0xffffffffu, tmax0, 1));
        tmax0 = fmaxf(tmax0, __shfl_xor_sync(0xffffffffu, tmax0, 2));
        tmax1 = fmaxf(tmax1, __shfl_xor_sync(0xffffffffu, tmax1, 1));
        tmax1 = fmaxf(tmax1, __shfl_xor_sync(0xffffffffu, tmax1, 2));
        const float mn0 = fmaxf(m0, tmax0);
        const float mn1 = fmaxf(m1, tmax1);
        const float corr0 = __expf(m0 - mn0);
        const float corr1 = __expf(m1 - mn1);
        m0 = mn0; m1 = mn1;
#pragma unroll
        for (int nt = 0; nt < 8; nt++) {
            O[nt][0] *= corr0; O[nt][1] *= corr0;
            O[nt][2] *= corr1; O[nt][3] *= corr1;
        }

        float sum0 = 0.f, sum1 = 0.f;
        uint32_t phi[4][4], plo[4][4];
#pragma unroll
        for (int bt = 0; bt < 4; bt++) {
            float p00 = __expf(S[2 * bt][0] - mn0), p01 = __expf(S[2 * bt][1] - mn0);
            float p02 = __expf(S[2 * bt][2] - mn1), p03 = __expf(S[2 * bt][3] - mn1);
            float p10 = __expf(S[2 * bt + 1][0] - mn0), p11 = __expf(S[2 * bt + 1][1] - mn0);
            float p12 = __expf(S[2 * bt + 1][2] - mn1), p13 = __expf(S[2 * bt + 1][3] - mn1);
            sum0 += p00 + p01 + p10 + p11;
            sum1 += p02 + p03 + p12 + p13;
            pack_pair(p00, p01, phi[bt][0], plo[bt][0]);
            pack_pair(p02, p03, phi[bt][1], plo[bt][1]);
            pack_pair(p10, p11, phi[bt][2], plo[bt][2]);
            pack_pair(p12, p13, phi[bt][3], plo[bt][3]);
        }
        sum0 += __shfl_xor_sync(0xffffffffu, sum0, 1);
        sum0 += __shfl_xor_sync(0xffffffffu, sum0, 2);
        sum1 += __shfl_xor_sync(0xffffffffu, sum1, 1);
        sum1 += __shfl_xor_sync(0xffffffffu, sum1, 2);
        l0 = l0 * corr0 + sum0;
        l1 = l1 * corr1 + sum1;

        // AV: phi*Vhi + plo*Vhi, then phi*Vlo
#pragma unroll
        for (int kc = 0; kc < 4; kc++) {
            uint32_t vb[4][4];
#pragma unroll
            for (int ntp = 0; ntp < 4; ntp++) {
                int key = kc * 16 + ((lane >> 3) & 1) * 8 + (lane & 7);
                int col = ntp * 16 + ((lane >> 4) << 3);
                ldsm_x4t(vb[ntp][0], vb[ntp][1], vb[ntp][2], vb[ntp][3],
                         smem_u32(&Vst[key * APAD + col]));
            }
#pragma unroll
            for (int ntp = 0; ntp < 4; ntp++) {
                mma16816(O[2 * ntp],     phi[kc], &vb[ntp][0]);
                mma16816(O[2 * ntp + 1], phi[kc], &vb[ntp][2]);
                mma16816(O[2 * ntp],     plo[kc], &vb[ntp][0]);
                mma16816(O[2 * ntp + 1], plo[kc], &vb[ntp][2]);
            }
        }
#pragma unroll
        for (int kc = 0; kc < 4; kc++) {
            uint32_t vb[4][4];
#pragma unroll
            for (int ntp = 0; ntp < 4; ntp++) {
                int key = kc * 16 + ((lane >> 3) & 1) * 8 + (lane & 7);
                int col = 64 + ntp * 16 + ((lane >> 4) << 3);
                ldsm_x4t(vb[ntp][0], vb[ntp][1], vb[ntp][2], vb[ntp][3],
                         smem_u32(&Vst[key * APAD + col]));
            }
#pragma unroll
            for (int ntp = 0; ntp < 4; ntp++) {
                mma16816(O[2 * ntp],     phi[kc], &vb[ntp][0]);
                mma16816(O[2 * ntp + 1], phi[kc], &vb[ntp][2]);
            }
        }
    }

    // write ctx in split-bf16 format directly: cs[M][2048]
    const float inv0 = 1.f / l0;
    const float inv1 = 1.f / l1;
    const int b = bh >> 4, h = bh & 15;
    const int s0 = qb * 128 + wid * 16 + (lane >> 2);
    const long row0 = (long)(b * SEQ + s0) * KSP;
    const long row1 = row0 + (long)8 * KSP;
#pragma unroll
    for (int nt = 0; nt < 8; nt++) {
        int c = h * HDIM + nt * 8 + 2 * (lane & 3);
        uint32_t hi, lo;
        pack_pair(O[nt][0] * inv0, O[nt][1] * inv0, hi, lo);
        *(uint32_t*)&cs[row0 + c] = hi;
        *(uint32_t*)&cs[row0 + 1024 + c] = lo;
        pack_pair(O[nt][2] * inv1, O[nt][3] * inv1, hi, lo);
        *(uint32_t*)&cs[row1 + c] = hi;
        *(uint32_t*)&cs[row1 + 1024 + c] = lo;
    }
}

// ---------------- launch ----------------
extern "C" void kernel_launch(void* const* d_in, const int* in_sizes, int n_in,
                              void* d_out, int out_size)
{
    const float* x  = (const float*)d_in[0];
    const float* Wq = (const float*)d_in[1];
    const float* bq = (const float*)d_in[2];
    const float* Wk = (const float*)d_in[3];
    const float* bk = (const float*)d_in[4];
    const float* Wv = (const float*)d_in[5];
    const float* bv = (const float*)d_in[6];
    const float* Wo = (const float*)d_in[7];
    const float* bo = (const float*)d_in[8];
    const int* rope_start = (const int*)d_in[9];
    float* out = (float*)d_out;

    __nv_bfloat16 *xs, *wtq, *wtk, *wtv, *wto, *qsp, *ksp, *vsp, *cs;
    cudaGetSymbolAddress((void**)&xs,  g_xs);
    cudaGetSymbolAddress((void**)&wtq, g_wtq);
    cudaGetSymbolAddress((void**)&wtk, g_wtk);
    cudaGetSymbolAddress((void**)&wtv, g_wtv);
    cudaGetSymbolAddress((void**)&wto, g_wto);
    cudaGetSymbolAddress((void**)&qsp, g_qsp);
    cudaGetSymbolAddress((void**)&ksp, g_ksp);
    cudaGetSymbolAddress((void**)&vsp, g_vsp);
    cudaGetSymbolAddress((void**)&cs,  g_cs);

    static bool attr_done = false;
    if (!attr_done) {
        cudaFuncSetAttribute(gemm_mma<0>, cudaFuncAttributeMaxDynamicSharedMemorySize, GEMM_SMEM);
        cudaFuncSetAttribute(gemm_mma<2>, cudaFuncAttributeMaxDynamicSharedMemorySize, GEMM_SMEM);
        cudaFuncSetAttribute(gemm_mma<3>, cudaFuncAttributeMaxDynamicSharedMemorySize, GEMM_SMEM);
        cudaFuncSetAttribute(attn_mma,    cudaFuncAttributeMaxDynamicSharedMemorySize, ATTN_SMEM);
        attr_done = true;
    }

    // 1: input split
    split_kernel<<<MTOT, 256>>>(x, xs);
    // 2: fused weight splits
    dim3 wgrid(32, 32, 4), wblock(32, 8);
    wsplit_kernel<<<wgrid, wblock>>>(Wq, Wk, Wv, Wo, wtq, wtk, wtv, wto);

    // 3-5: projections (tensor core, fused rope+scale+split epilogue)
    dim3 ggrid(DMODEL / 128, MTOT / 128);     // (8, 64)
    gemm_mma<3><<<ggrid, 256, GEMM_SMEM>>>(xs, wtq, bq, qsp, rope_start, 0.125f);
    gemm_mma<3><<<ggrid, 256, GEMM_SMEM>>>(xs, wtk, bk, ksp, rope_start, 1.0f);
    gemm_mma<2><<<ggrid, 256, GEMM_SMEM>>>(xs, wtv, bv, vsp, rope_start, 1.0f);

    // 6: attention (direct split-bf16 ctx output)
    attn_mma<<<dim3(SEQ / 128, BATCH * NHEAD), 256, ATTN_SMEM>>>(qsp, ksp, vsp, cs);

    // 7: output projection
    gemm_mma<0><<<ggrid, 256, GEMM_SMEM>>>(cs, wto, bo, out, rope_start, 1.0f);
}